// round 11
// baseline (speedup 1.0000x reference)
#include <cuda_runtime.h>

// ---------------------------------------------------------------------------
// Fused 3-layer tanh RNN + FC head.  B=8192, T=80, D=32, H=64.
// CTA = 64 batch, 256 threads (8 warps, 2/SMSP), grid = 128.
//
// v6 = v3 (760us: broadcast h LDS.128, spread w LDS.64, syncwarp-only loop)
//   + tanh.approx.f32 (MUFU.TANH) replacing software tanhf in the recurrence
//   + merged input/recurrent accumulation loops (one k-loop per layer)
// Both changes shorten serial dependency chains; smem access pattern (the
// structurally-minimal 4 wavefronts/warp/k) is untouched.
// ---------------------------------------------------------------------------

#define B_TOT    8192
#define T_STEPS  80
#define D_IN     32
#define HDIM     64
#define BT       64          // batch tile per CTA
#define NTHREADS 256
#define P        68          // smem row pitch in floats

// smem layout offsets (in floats)
#define OFF_X    0
#define OFF_H0   (OFF_X    + D_IN * P)
#define OFF_H1   (OFF_H0   + HDIM * P)
#define OFF_H2   (OFF_H1   + HDIM * P)
#define OFF_WIH0 (OFF_H2   + HDIM * P)
#define OFF_WHH0 (OFF_WIH0 + D_IN * P)
#define OFF_WIH1 (OFF_WHH0 + HDIM * P)
#define OFF_WHH1 (OFF_WIH1 + HDIM * P)
#define OFF_WIH2 (OFF_WHH1 + HDIM * P)
#define OFF_WHH2 (OFF_WIH2 + HDIM * P)
#define OFF_BS   (OFF_WHH2 + HDIM * P)   // 3 x 64 combined biases
#define OFF_WFC  (OFF_BS   + 3 * HDIM)
#define OFF_BFC  (OFF_WFC  + HDIM)
#define SMEM_FLOATS (OFF_BFC + 1)

typedef unsigned long long u64;

// ---- packed fp32x2 helpers --------------------------------------------------
__device__ __forceinline__ u64 dup2(float v) {
    u64 r;
    asm("mov.b64 %0, {%1, %1};" : "=l"(r) : "f"(v));
    return r;
}
__device__ __forceinline__ float2 unpack2(u64 v) {
    float2 r;
    asm("mov.b64 {%0, %1}, %2;" : "=f"(r.x), "=f"(r.y) : "l"(v));
    return r;
}
#define FMA2(accv, av, bv) \
    asm("fma.rn.f32x2 %0, %1, %2, %0;" : "+l"(accv) : "l"(av), "l"(bv))

// ---- fast tanh via MUFU.TANH (sm_75+) --------------------------------------
__device__ __forceinline__ float tanh_fast(float x) {
    float y;
    asm("tanh.approx.f32 %0, %1;" : "=f"(y) : "f"(x));
    return y;
}

// ---- one merged k-iteration: acc += inT[k][b..] * WT[k][j..] ---------------
__device__ __forceinline__ void kstep(const float* __restrict__ inT,
                                      const float* __restrict__ WT,
                                      int k, int b0, int j0,
                                      u64 acc[4][2]) {
    double2 ha = *reinterpret_cast<const double2*>(inT + k * P + b0);
    double2 hb = *reinterpret_cast<const double2*>(inT + k * P + b0 + 4);
    float2 wv = *reinterpret_cast<const float2*>(WT + k * P + j0);
    u64 w0 = dup2(wv.x);
    u64 w1 = dup2(wv.y);
    u64 h01 = __double_as_longlong(ha.x);
    u64 h23 = __double_as_longlong(ha.y);
    u64 h45 = __double_as_longlong(hb.x);
    u64 h67 = __double_as_longlong(hb.y);
    FMA2(acc[0][0], h01, w0); FMA2(acc[0][1], h01, w1);
    FMA2(acc[1][0], h23, w0); FMA2(acc[1][1], h23, w1);
    FMA2(acc[2][0], h45, w0); FMA2(acc[2][1], h45, w1);
    FMA2(acc[3][0], h67, w0); FMA2(acc[3][1], h67, w1);
}

// ---- one RNN layer step with MERGED in/rec k-loop (warp-private in batch) --
// in stream: KIN rows of inT * WinT;  rec stream: 64 rows of hT * WhhT.
template <int KIN>
__device__ __forceinline__ void layer_step(const float* __restrict__ inT,
                                           const float* __restrict__ WinT,
                                           float* __restrict__ hT,
                                           const float* __restrict__ WhhT,
                                           const float* __restrict__ bs,
                                           int b0, int j0) {
    u64 acc[4][2];
    float2 bv = *reinterpret_cast<const float2*>(bs + j0);
#pragma unroll
    for (int i = 0; i < 4; ++i) { acc[i][0] = dup2(bv.x); acc[i][1] = dup2(bv.y); }

    // merged region: both streams per iteration (4 independent LDS in flight)
#pragma unroll 8
    for (int k = 0; k < KIN; ++k) {
        kstep(inT, WinT, k, b0, j0, acc);
        kstep(hT,  WhhT, k, b0, j0, acc);
    }
    // remainder: recurrent stream only
#pragma unroll 8
    for (int k = KIN; k < HDIM; ++k) {
        kstep(hT, WhhT, k, b0, j0, acc);
    }

    __syncwarp();  // all lanes' reads of old hT done before overwrite

    float2 p0 = unpack2(acc[0][0]), p1 = unpack2(acc[1][0]);
    float2 p2 = unpack2(acc[2][0]), p3 = unpack2(acc[3][0]);
    *reinterpret_cast<float4*>(hT + j0 * P + b0) =
        make_float4(tanh_fast(p0.x), tanh_fast(p0.y),
                    tanh_fast(p1.x), tanh_fast(p1.y));
    *reinterpret_cast<float4*>(hT + j0 * P + b0 + 4) =
        make_float4(tanh_fast(p2.x), tanh_fast(p2.y),
                    tanh_fast(p3.x), tanh_fast(p3.y));

    float2 q0 = unpack2(acc[0][1]), q1 = unpack2(acc[1][1]);
    float2 q2 = unpack2(acc[2][1]), q3 = unpack2(acc[3][1]);
    *reinterpret_cast<float4*>(hT + (j0 + 1) * P + b0) =
        make_float4(tanh_fast(q0.x), tanh_fast(q0.y),
                    tanh_fast(q1.x), tanh_fast(q1.y));
    *reinterpret_cast<float4*>(hT + (j0 + 1) * P + b0 + 4) =
        make_float4(tanh_fast(q2.x), tanh_fast(q2.y),
                    tanh_fast(q3.x), tanh_fast(q3.y));

    __syncwarp();  // new h visible to all lanes of this warp
}

// ---- transpose weight [64][K] row-major -> WT[k*P + j] ----------------------
__device__ __forceinline__ void load_wT(const float* __restrict__ W,
                                        float* __restrict__ WT, int K, int tid) {
    for (int idx = tid; idx < HDIM * K; idx += NTHREADS) {
        int j = idx / K;
        int k = idx - j * K;
        WT[k * P + j] = W[idx];
    }
}

__global__ void __launch_bounds__(NTHREADS, 1)
rnn_fused_v6(const float* __restrict__ x,
             const float* __restrict__ Wih0, const float* __restrict__ Whh0,
             const float* __restrict__ bih0, const float* __restrict__ bhh0,
             const float* __restrict__ Wih1, const float* __restrict__ Whh1,
             const float* __restrict__ bih1, const float* __restrict__ bhh1,
             const float* __restrict__ Wih2, const float* __restrict__ Whh2,
             const float* __restrict__ bih2, const float* __restrict__ bhh2,
             const float* __restrict__ Wfc,  const float* __restrict__ bfc,
             float* __restrict__ out) {
    extern __shared__ float smem[];
    const int tid   = threadIdx.x;
    const int bbase = blockIdx.x * BT;

    // ---- one-time setup: weights (transposed), biases, zero hidden states
    load_wT(Wih0, smem + OFF_WIH0, D_IN, tid);
    load_wT(Whh0, smem + OFF_WHH0, HDIM, tid);
    load_wT(Wih1, smem + OFF_WIH1, HDIM, tid);
    load_wT(Whh1, smem + OFF_WHH1, HDIM, tid);
    load_wT(Wih2, smem + OFF_WIH2, HDIM, tid);
    load_wT(Whh2, smem + OFF_WHH2, HDIM, tid);
    if (tid < 3 * HDIM) {
        int l = tid >> 6, j = tid & 63;
        const float* bi = (l == 0) ? bih0 : (l == 1) ? bih1 : bih2;
        const float* bh = (l == 0) ? bhh0 : (l == 1) ? bhh1 : bhh2;
        smem[OFF_BS + tid] = bi[j] + bh[j];
    }
    if (tid < HDIM) smem[OFF_WFC + tid] = Wfc[tid];
    if (tid == 0)   smem[OFF_BFC] = bfc[0];
    for (int i = tid; i < 3 * HDIM * P; i += NTHREADS) smem[OFF_H0 + i] = 0.0f;

    // ---- x prefetch: each thread owns 8 consecutive floats of one row
    // (warp-private: warp w's threads cover exactly batch columns w*8..w*8+7)
    const int xb = tid >> 2;            // local batch index 0..63
    const int xd = (tid & 3) * 8;       // d offset 0,8,16,24
    const float* xp = x + (size_t)(bbase + xb) * (T_STEPS * D_IN) + xd;
    float4 xr0 = *reinterpret_cast<const float4*>(xp);
    float4 xr1 = *reinterpret_cast<const float4*>(xp + 4);

    __syncthreads();   // setup visible to all warps

    const int lane = tid & 31;
    const int b0   = (tid >> 5) * 8;    // warp's batch sub-tile
    const int j0   = lane * 2;          // lane's hidden-unit pair

    for (int t = 0; t < T_STEPS; ++t) {
        // stage x_t into smem (transposed: xT[d][b]); prefetch x_{t+1}
        float* xc = smem + OFF_X + xb;
        xc[(xd + 0) * P] = xr0.x; xc[(xd + 1) * P] = xr0.y;
        xc[(xd + 2) * P] = xr0.z; xc[(xd + 3) * P] = xr0.w;
        xc[(xd + 4) * P] = xr1.x; xc[(xd + 5) * P] = xr1.y;
        xc[(xd + 6) * P] = xr1.z; xc[(xd + 7) * P] = xr1.w;
        if (t + 1 < T_STEPS) {
            xr0 = *reinterpret_cast<const float4*>(xp + (t + 1) * D_IN);
            xr1 = *reinterpret_cast<const float4*>(xp + (t + 1) * D_IN + 4);
        }
        __syncwarp();   // warp's x columns staged

        layer_step<D_IN>(smem + OFF_X,  smem + OFF_WIH0, smem + OFF_H0,
                         smem + OFF_WHH0, smem + OFF_BS,            b0, j0);
        layer_step<HDIM>(smem + OFF_H0, smem + OFF_WIH1, smem + OFF_H1,
                         smem + OFF_WHH1, smem + OFF_BS + HDIM,     b0, j0);
        layer_step<HDIM>(smem + OFF_H1, smem + OFF_WIH2, smem + OFF_H2,
                         smem + OFF_WHH2, smem + OFF_BS + 2 * HDIM, b0, j0);
    }

    __syncthreads();   // FC head reads h2 across warp boundaries

    // ---- FC head: out[b] = h2_last[b] . Wfc + bfc (exact fp32 math) --------
    if (tid < BT) {
        float s = smem[OFF_BFC];
        const float* h2 = smem + OFF_H2;
        const float* wf = smem + OFF_WFC;
#pragma unroll
        for (int j = 0; j < HDIM; ++j) s += h2[j * P + tid] * wf[j];
        out[bbase + tid] = s;
    }
}

extern "C" void kernel_launch(void* const* d_in, const int* in_sizes, int n_in,
                              void* d_out, int out_size) {
    (void)in_sizes; (void)n_in; (void)out_size;
    const size_t smem_bytes = SMEM_FLOATS * sizeof(float);
    cudaFuncSetAttribute(rnn_fused_v6,
                         cudaFuncAttributeMaxDynamicSharedMemorySize,
                         (int)smem_bytes);
    rnn_fused_v6<<<B_TOT / BT, NTHREADS, smem_bytes>>>(
        (const float*)d_in[0],
        (const float*)d_in[1],  (const float*)d_in[2],
        (const float*)d_in[3],  (const float*)d_in[4],
        (const float*)d_in[5],  (const float*)d_in[6],
        (const float*)d_in[7],  (const float*)d_in[8],
        (const float*)d_in[9],  (const float*)d_in[10],
        (const float*)d_in[11], (const float*)d_in[12],
        (const float*)d_in[13], (const float*)d_in[14],
        (float*)d_out);
}

// round 12
// speedup vs baseline: 1.6230x; 1.6230x over previous
#include <cuda_runtime.h>

// ---------------------------------------------------------------------------
// Fused 3-layer tanh RNN + FC head, single persistent time loop per CTA.
//   B=8192, T=80, D=32, H=64.  CTA = 64 batch elems, 256 threads, grid=128.
//
// v7 = v3 (760us skeleton: broadcast h LDS.128 + spread w LDS.64, separate
// input/recurrent accum loops, warp-private batch tiles, __syncwarp-only
// time loop) with ONE change: software tanhf -> tanh.approx.f32 (MUFU.TANH).
// v6 proved the accuracy is fine (rel_err 1.1e-5 << 1e-3) but its merged
// k-loop regressed scheduling; this keeps v3's loop structure untouched.
// ---------------------------------------------------------------------------

#define B_TOT    8192
#define T_STEPS  80
#define D_IN     32
#define HDIM     64
#define BT       64          // batch tile per CTA
#define NTHREADS 256
#define P        68          // smem row pitch in floats

// smem layout offsets (in floats)
#define OFF_X    0
#define OFF_H0   (OFF_X    + D_IN * P)
#define OFF_H1   (OFF_H0   + HDIM * P)
#define OFF_H2   (OFF_H1   + HDIM * P)
#define OFF_WIH0 (OFF_H2   + HDIM * P)
#define OFF_WHH0 (OFF_WIH0 + D_IN * P)
#define OFF_WIH1 (OFF_WHH0 + HDIM * P)
#define OFF_WHH1 (OFF_WIH1 + HDIM * P)
#define OFF_WIH2 (OFF_WHH1 + HDIM * P)
#define OFF_WHH2 (OFF_WIH2 + HDIM * P)
#define OFF_BS   (OFF_WHH2 + HDIM * P)   // 3 x 64 combined biases
#define OFF_WFC  (OFF_BS   + 3 * HDIM)
#define OFF_BFC  (OFF_WFC  + HDIM)
#define SMEM_FLOATS (OFF_BFC + 1)

// ---- packed fp32x2 helpers --------------------------------------------------
__device__ __forceinline__ unsigned long long dup2(float v) {
    unsigned long long r;
    asm("mov.b64 %0, {%1, %1};" : "=l"(r) : "f"(v));
    return r;
}
__device__ __forceinline__ float2 unpack2(unsigned long long v) {
    float2 r;
    asm("mov.b64 {%0, %1}, %2;" : "=f"(r.x), "=f"(r.y) : "l"(v));
    return r;
}
#define FMA2(accv, av, bv) \
    asm("fma.rn.f32x2 %0, %1, %2, %0;" : "+l"(accv) : "l"(av), "l"(bv))

// ---- fast tanh via MUFU.TANH (sm_75+); v6 measured rel_err 1.1e-5 ----------
__device__ __forceinline__ float tanh_fast(float x) {
    float y;
    asm("tanh.approx.f32 %0, %1;" : "=f"(y) : "f"(x));
    return y;
}

// ---- outer-product accumulate over K: acc[b-pair][j] += inT[k][b] * WT[k][j]
template <int K>
__device__ __forceinline__ void accum(const float* __restrict__ inT,
                                      const float* __restrict__ WT,
                                      int b0, int j0,
                                      unsigned long long acc[4][2]) {
#pragma unroll 16
    for (int k = 0; k < K; ++k) {
        double2 ha = *reinterpret_cast<const double2*>(inT + k * P + b0);
        double2 hb = *reinterpret_cast<const double2*>(inT + k * P + b0 + 4);
        float2 wv = *reinterpret_cast<const float2*>(WT + k * P + j0);
        unsigned long long w0 = dup2(wv.x);
        unsigned long long w1 = dup2(wv.y);
        unsigned long long h01 = __double_as_longlong(ha.x);
        unsigned long long h23 = __double_as_longlong(ha.y);
        unsigned long long h45 = __double_as_longlong(hb.x);
        unsigned long long h67 = __double_as_longlong(hb.y);
        FMA2(acc[0][0], h01, w0); FMA2(acc[0][1], h01, w1);
        FMA2(acc[1][0], h23, w0); FMA2(acc[1][1], h23, w1);
        FMA2(acc[2][0], h45, w0); FMA2(acc[2][1], h45, w1);
        FMA2(acc[3][0], h67, w0); FMA2(acc[3][1], h67, w1);
    }
}

// ---- one RNN layer step: h_out = tanh(bias + WinT^T in + WhhT^T h_out_prev)
// Warp-private: all smem traffic touches only this warp's batch columns.
template <int KIN>
__device__ __forceinline__ void layer_step(const float* __restrict__ inT,
                                           const float* __restrict__ WinT,
                                           float* __restrict__ hT,
                                           const float* __restrict__ WhhT,
                                           const float* __restrict__ bs,
                                           int b0, int j0) {
    unsigned long long acc[4][2];
    float2 bv = *reinterpret_cast<const float2*>(bs + j0);
#pragma unroll
    for (int i = 0; i < 4; ++i) { acc[i][0] = dup2(bv.x); acc[i][1] = dup2(bv.y); }

    accum<KIN>(inT, WinT, b0, j0, acc);   // input projection
    accum<HDIM>(hT,  WhhT, b0, j0, acc);  // recurrent part (reads old h)

    __syncwarp();  // all lanes' reads of old hT columns done before overwrite

    float2 p0 = unpack2(acc[0][0]), p1 = unpack2(acc[1][0]);
    float2 p2 = unpack2(acc[2][0]), p3 = unpack2(acc[3][0]);
    *reinterpret_cast<float4*>(hT + j0 * P + b0) =
        make_float4(tanh_fast(p0.x), tanh_fast(p0.y),
                    tanh_fast(p1.x), tanh_fast(p1.y));
    *reinterpret_cast<float4*>(hT + j0 * P + b0 + 4) =
        make_float4(tanh_fast(p2.x), tanh_fast(p2.y),
                    tanh_fast(p3.x), tanh_fast(p3.y));

    float2 q0 = unpack2(acc[0][1]), q1 = unpack2(acc[1][1]);
    float2 q2 = unpack2(acc[2][1]), q3 = unpack2(acc[3][1]);
    *reinterpret_cast<float4*>(hT + (j0 + 1) * P + b0) =
        make_float4(tanh_fast(q0.x), tanh_fast(q0.y),
                    tanh_fast(q1.x), tanh_fast(q1.y));
    *reinterpret_cast<float4*>(hT + (j0 + 1) * P + b0 + 4) =
        make_float4(tanh_fast(q2.x), tanh_fast(q2.y),
                    tanh_fast(q3.x), tanh_fast(q3.y));

    __syncwarp();  // new h visible to all lanes of this warp
}

// ---- transpose weight [64][K] row-major -> WT[k*P + j] ----------------------
__device__ __forceinline__ void load_wT(const float* __restrict__ W,
                                        float* __restrict__ WT, int K, int tid) {
    for (int idx = tid; idx < HDIM * K; idx += NTHREADS) {
        int j = idx / K;
        int k = idx - j * K;
        WT[k * P + j] = W[idx];
    }
}

__global__ void __launch_bounds__(NTHREADS, 1)
rnn_fused_v7(const float* __restrict__ x,
             const float* __restrict__ Wih0, const float* __restrict__ Whh0,
             const float* __restrict__ bih0, const float* __restrict__ bhh0,
             const float* __restrict__ Wih1, const float* __restrict__ Whh1,
             const float* __restrict__ bih1, const float* __restrict__ bhh1,
             const float* __restrict__ Wih2, const float* __restrict__ Whh2,
             const float* __restrict__ bih2, const float* __restrict__ bhh2,
             const float* __restrict__ Wfc,  const float* __restrict__ bfc,
             float* __restrict__ out) {
    extern __shared__ float smem[];
    const int tid   = threadIdx.x;
    const int bbase = blockIdx.x * BT;

    // ---- one-time setup: weights (transposed), biases, zero hidden states
    load_wT(Wih0, smem + OFF_WIH0, D_IN, tid);
    load_wT(Whh0, smem + OFF_WHH0, HDIM, tid);
    load_wT(Wih1, smem + OFF_WIH1, HDIM, tid);
    load_wT(Whh1, smem + OFF_WHH1, HDIM, tid);
    load_wT(Wih2, smem + OFF_WIH2, HDIM, tid);
    load_wT(Whh2, smem + OFF_WHH2, HDIM, tid);
    if (tid < 3 * HDIM) {
        int l = tid >> 6, j = tid & 63;
        const float* bi = (l == 0) ? bih0 : (l == 1) ? bih1 : bih2;
        const float* bh = (l == 0) ? bhh0 : (l == 1) ? bhh1 : bhh2;
        smem[OFF_BS + tid] = bi[j] + bh[j];
    }
    if (tid < HDIM) smem[OFF_WFC + tid] = Wfc[tid];
    if (tid == 0)   smem[OFF_BFC] = bfc[0];
    for (int i = tid; i < 3 * HDIM * P; i += NTHREADS) smem[OFF_H0 + i] = 0.0f;

    // ---- x prefetch: each thread owns 8 consecutive floats of one row
    // (warp-private: warp w's threads cover exactly batch columns w*8..w*8+7)
    const int xb = tid >> 2;            // local batch index 0..63
    const int xd = (tid & 3) * 8;       // d offset 0,8,16,24
    const float* xp = x + (size_t)(bbase + xb) * (T_STEPS * D_IN) + xd;
    float4 xr0 = *reinterpret_cast<const float4*>(xp);
    float4 xr1 = *reinterpret_cast<const float4*>(xp + 4);

    __syncthreads();   // weights/biases/zeroed state visible to all warps

    const int lane = tid & 31;
    const int b0   = (tid >> 5) * 8;    // warp's batch sub-tile
    const int j0   = lane * 2;          // lane's hidden-unit pair

    for (int t = 0; t < T_STEPS; ++t) {
        // stage x_t into smem (transposed: xT[d][b]); prefetch x_{t+1}
        float* xc = smem + OFF_X + xb;
        xc[(xd + 0) * P] = xr0.x; xc[(xd + 1) * P] = xr0.y;
        xc[(xd + 2) * P] = xr0.z; xc[(xd + 3) * P] = xr0.w;
        xc[(xd + 4) * P] = xr1.x; xc[(xd + 5) * P] = xr1.y;
        xc[(xd + 6) * P] = xr1.z; xc[(xd + 7) * P] = xr1.w;
        if (t + 1 < T_STEPS) {
            xr0 = *reinterpret_cast<const float4*>(xp + (t + 1) * D_IN);
            xr1 = *reinterpret_cast<const float4*>(xp + (t + 1) * D_IN + 4);
        }
        __syncwarp();   // warp's x columns staged

        layer_step<D_IN>(smem + OFF_X,  smem + OFF_WIH0, smem + OFF_H0,
                         smem + OFF_WHH0, smem + OFF_BS,            b0, j0);
        layer_step<HDIM>(smem + OFF_H0, smem + OFF_WIH1, smem + OFF_H1,
                         smem + OFF_WHH1, smem + OFF_BS + HDIM,     b0, j0);
        layer_step<HDIM>(smem + OFF_H1, smem + OFF_WIH2, smem + OFF_H2,
                         smem + OFF_WHH2, smem + OFF_BS + 2 * HDIM, b0, j0);
    }

    __syncthreads();   // FC head reads h2 across warp boundaries

    // ---- FC head: out[b] = h2_last[b] . Wfc + bfc (exact fp32 math) --------
    if (tid < BT) {
        float s = smem[OFF_BFC];
        const float* h2 = smem + OFF_H2;
        const float* wf = smem + OFF_WFC;
#pragma unroll
        for (int j = 0; j < HDIM; ++j) s += h2[j * P + tid] * wf[j];
        out[bbase + tid] = s;
    }
}

extern "C" void kernel_launch(void* const* d_in, const int* in_sizes, int n_in,
                              void* d_out, int out_size) {
    (void)in_sizes; (void)n_in; (void)out_size;
    const size_t smem_bytes = SMEM_FLOATS * sizeof(float);
    cudaFuncSetAttribute(rnn_fused_v7,
                         cudaFuncAttributeMaxDynamicSharedMemorySize,
                         (int)smem_bytes);
    rnn_fused_v7<<<B_TOT / BT, NTHREADS, smem_bytes>>>(
        (const float*)d_in[0],
        (const float*)d_in[1],  (const float*)d_in[2],
        (const float*)d_in[3],  (const float*)d_in[4],
        (const float*)d_in[5],  (const float*)d_in[6],
        (const float*)d_in[7],  (const float*)d_in[8],
        (const float*)d_in[9],  (const float*)d_in[10],
        (const float*)d_in[11], (const float*)d_in[12],
        (const float*)d_in[13], (const float*)d_in[14],
        (float*)d_out);
}